// round 8
// baseline (speedup 1.0000x reference)
#include <cuda_runtime.h>
#include <math_constants.h>
#include <cstdint>

// Shapes: V=1024 fixed; B,L,T from in_sizes. Scratch for B<=64, T<=1000, S<=256.
#define VOCAB      1024
#define MAXB       64
#define MAXTP      1048          // padded T rows ((T+39) & ~7)
#define SP         256           // padded extended-state stride (>= S = 2L+1), 8 per lane
#define RING       32            // smem ring slots (rows) in consumer
#define FULLMASK   0xffffffffu

#define LOG2E_F 1.4426950408889634f
#define LN2_F   0.6931471805599453f

typedef unsigned long long ull;

static __device__ __forceinline__ float fex2(float x) {
    float y; asm("ex2.approx.f32 %0, %1;" : "=f"(y) : "f"(x)); return y;
}

#define CP16(sm, gp) \
    asm volatile("cp.async.cg.shared.global [%0], [%1], 16;" :: "r"(sm), "l"(gp))
#define CP_COMMIT() \
    asm volatile("cp.async.commit_group;" ::: "memory")
#define CP_WAIT_2() \
    asm volatile("cp.async.wait_group 2;" ::: "memory")
#define CP_WAIT_ALL() \
    asm volatile("cp.async.wait_all;" ::: "memory")

// Scratch
__device__ float         g_p[(size_t)MAXB * MAXTP * SP];
__device__ unsigned char g_flag[(size_t)MAXB * MAXTP];
__device__ float         g_loss[MAXB];

static __device__ __forceinline__ ull ld_flags_acq(const unsigned char* p) {
    ull v;
    asm volatile("ld.acquire.gpu.global.b64 %0, [%1];" : "=l"(v) : "l"(p) : "memory");
    return v;
}

// ---------------------------------------------------------------------------
// Kernel 0: reset flags. Rows t < T start at 0; pad rows (t >= T) pre-set to 1
// so the consumer's group polls never wait on rows that are never produced.
// ---------------------------------------------------------------------------
__global__ void init_flags_kernel(int B, int T, int TP)
{
    int i = blockIdx.x * 256 + threadIdx.x;
    int n = B * TP;
    if (i < n) {
        int t = i % TP;
        g_flag[i] = (t < T) ? 0 : 1;
    }
}

// ---------------------------------------------------------------------------
// Kernel 1 (fused): blockIdx < B -> CONSUMER (one warp: CTC forward scan).
// blockIdx >= B -> PRODUCER (8 warps, one softmax row each, t-major order).
// ---------------------------------------------------------------------------
__global__ void __launch_bounds__(256, 3)
fused_kernel(const float* __restrict__ pred,
             const int*   __restrict__ plen,
             const int*   __restrict__ gt,
             const int*   __restrict__ gtl,
             int B, int T, int TP, int L, int S, int NT)
{
    // ======================= PRODUCER =======================
    if ((int)blockIdx.x >= B) {
        const int rank = ((int)blockIdx.x - B) * 8 + ((int)threadIdx.x >> 5);
        if (rank >= NT) return;
        const int lane = threadIdx.x & 31;
        const int t = rank / B;               // t-major: all batches of t together
        const int b = rank - t * B;

        const float* __restrict__ p = pred + ((size_t)b * T + t) * VOCAB;

        float4 v[8];
        #pragma unroll
        for (int k = 0; k < 8; k++)
            v[k] = *reinterpret_cast<const float4*>(p + lane * 4 + k * 128);

        float mx = -CUDART_INF_F;
        #pragma unroll
        for (int k = 0; k < 8; k++)
            mx = fmaxf(mx, fmaxf(fmaxf(v[k].x, v[k].y), fmaxf(v[k].z, v[k].w)));
        #pragma unroll
        for (int o = 16; o; o >>= 1)
            mx = fmaxf(mx, __shfl_xor_sync(FULLMASK, mx, o));
        const float c = mx * LOG2E_F;

        float sum = 0.f;
        #pragma unroll
        for (int k = 0; k < 8; k++) {
            sum += fex2(fmaf(v[k].x, LOG2E_F, -c)) + fex2(fmaf(v[k].y, LOG2E_F, -c))
                 + fex2(fmaf(v[k].z, LOG2E_F, -c)) + fex2(fmaf(v[k].w, LOG2E_F, -c));
        }
        #pragma unroll
        for (int o = 16; o; o >>= 1)
            sum += __shfl_xor_sync(FULLMASK, sum, o);
        const float inv = __frcp_rn(sum);

        float* __restrict__ out = g_p + ((size_t)b * TP + t) * SP;
        const int* __restrict__ gtb = gt + (size_t)b * L;
        float val[8];
        #pragma unroll
        for (int j = 0; j < 8; j++) {
            int s = lane * 8 + j;
            float r = 0.f;
            if (s < S) {
                int lab = 0;
                if (s & 1) {
                    int idx = (s >> 1); if (idx > L - 1) idx = L - 1;
                    lab = gtb[idx];
                }
                r = fex2(fmaf(__ldg(p + lab), LOG2E_F, -c)) * inv;
            }
            val[j] = r;
        }
        *reinterpret_cast<float4*>(out + lane * 8)     = make_float4(val[0], val[1], val[2], val[3]);
        *reinterpret_cast<float4*>(out + lane * 8 + 4) = make_float4(val[4], val[5], val[6], val[7]);

        // Publish: all lanes' stores executed, then fence + flag.
        __syncwarp();
        if (lane == 0) {
            __threadfence();
            asm volatile("st.relaxed.gpu.global.u8 [%0], %1;"
                         :: "l"(g_flag + (size_t)b * TP + t), "h"((unsigned short)1)
                         : "memory");
        }
        return;
    }

    // ======================= CONSUMER =======================
    __shared__ float ring[RING][SP];     // 32 KB
    if (threadIdx.x >= 32) return;       // single active warp

    const int b    = blockIdx.x;
    const int lane = threadIdx.x;
    const int ilen = min(plen[b], T);
    const int tl   = gtl[b];
    const float* __restrict__ Pb = g_p + (size_t)b * TP * SP + lane * 8;
    const int* __restrict__ gtb = gt + (size_t)b * L;
    const unsigned char* flg = g_flag + (size_t)b * TP;
    const unsigned int rb =
        (unsigned int)__cvta_generic_to_shared(ring) + (unsigned int)(lane * 32);
    const ull RDY = 0x0101010101010101ull;

    // Static skip masks
    float m[8];
    #pragma unroll
    for (int j = 0; j < 8; j++) {
        int s = lane * 8 + j;
        float mm = 0.f;
        if (s >= 2 && (s & 1) && s < S) {
            int lab = gtb[s >> 1], lm2 = gtb[(s >> 1) - 1];
            mm = (lab != 0 && lab != lm2) ? 1.f : 0.f;
        }
        m[j] = mm;
    }

    int   El = 0;
    float f  = (lane == 0) ? 0.f : 1.f;
    const int nsteps = ilen - 1;

#define CTC_STEP(Q0, Q1)                                                    \
    do {                                                                     \
        float u7 = __shfl_up_sync(FULLMASK, a[7], 1) * f;                    \
        float u6 = __shfl_up_sync(FULLMASK, a[6], 1) * f;                    \
        float n0 = fmaf(m[0], u6,   a[0] + u7)   * (Q0).x;                   \
        float n1 = fmaf(m[1], u7,   a[1] + a[0]) * (Q0).y;                   \
        float n2 = fmaf(m[2], a[0], a[2] + a[1]) * (Q0).z;                   \
        float n3 = fmaf(m[3], a[1], a[3] + a[2]) * (Q0).w;                   \
        float n4 = fmaf(m[4], a[2], a[4] + a[3]) * (Q1).x;                   \
        float n5 = fmaf(m[5], a[3], a[5] + a[4]) * (Q1).y;                   \
        float n6 = fmaf(m[6], a[4], a[6] + a[5]) * (Q1).z;                   \
        float n7 = fmaf(m[7], a[5], a[7] + a[6]) * (Q1).w;                   \
        a[0]=n0; a[1]=n1; a[2]=n2; a[3]=n3; a[4]=n4; a[5]=n5; a[6]=n6; a[7]=n7; \
    } while (0)

#define CTC_RENORM()                                                        \
    do {                                                                     \
        float mx = fmaxf(fmaxf(fmaxf(a[0], a[1]), fmaxf(a[2], a[3])),       \
                         fmaxf(fmaxf(a[4], a[5]), fmaxf(a[6], a[7])));       \
        bool nz = (mx > 0.f);                                                \
        int  e  = nz ? ((__float_as_int(mx) >> 23) - 127) : 0;               \
        int  Elp = El + e;                                                   \
        int  Eleft = __shfl_up_sync(FULLMASK, Elp, 1);                       \
        if (!nz && lane > 0) Elp = Eleft;                                    \
        if (nz) {                                                            \
            float sc = __int_as_float((127 - e) << 23);                      \
            _Pragma("unroll")                                                \
            for (int j = 0; j < 8; j++) a[j] *= sc;                          \
        }                                                                    \
        El = Elp;                                                            \
        int El2 = __shfl_up_sync(FULLMASK, El, 1);                           \
        int dE  = El2 - El;                                                  \
        if (lane == 0 || dE < -126) f = 0.f;                                 \
        else f = __int_as_float((min(dE, 126) + 127) << 23);                 \
    } while (0)

    // --- Prologue: poll + fill groups 0..2 (rows 0..23), preload group 3 ---
    for (int g = 0; g < 3; g++) {
        while (ld_flags_acq(flg + g * 8) != RDY) { }
        const float* gp = Pb + (size_t)(g * 8) * SP;
        #pragma unroll
        for (int r = 0; r < 8; r++) {
            unsigned int sa = rb + (unsigned int)(((g * 8 + r) & (RING - 1)) * (SP * 4));
            CP16(sa, gp); CP16(sa + 16, gp + 4);
            gp += SP;
        }
        CP_COMMIT();
    }
    ull nf = ld_flags_acq(flg + 3 * 8);   // preload group 3 flags

    CP_WAIT_2();                           // group 0 (rows 0..7) landed

    // alpha(t=0) from ring slot 0
    float a[8];
    #pragma unroll
    for (int j = 0; j < 8; j++) a[j] = 0.f;
    {
        float4 q = *reinterpret_cast<const float4*>(&ring[0][lane * 8]);
        if (lane == 0) {
            a[0] = q.x;
            a[1] = (tl > 0) ? q.y : 0.f;
        }
    }

    // q regs for step t=1 (row 1, in group 0)
    float4 q0 = make_float4(0.f, 0.f, 0.f, 0.f), q1 = q0;
    if (nsteps >= 1) {
        const float4* sp = reinterpret_cast<const float4*>(&ring[1][lane * 8]);
        q0 = sp[0]; q1 = sp[1];
    }

    int t = 1, mblk = 0;
    for (; t + 7 <= nsteps; t += 8, mblk++) {
        // Block boundary: fill group mblk+3 (rows 8(mblk+3) .. +7)
        if (nf != RDY) {
            do { nf = ld_flags_acq(flg + (mblk + 3) * 8); } while (nf != RDY);
        }
        {
            const float* gp = Pb + (size_t)((mblk + 3) * 8) * SP;
            #pragma unroll
            for (int r = 0; r < 8; r++) {
                unsigned int sa = rb +
                    (unsigned int)((((mblk + 3) * 8 + r) & (RING - 1)) * (SP * 4));
                CP16(sa, gp); CP16(sa + 16, gp + 4);
                gp += SP;
            }
            CP_COMMIT();
        }
        CP_WAIT_2();                       // groups <= mblk+1 landed
        nf = ld_flags_acq(flg + (mblk + 4) * 8);   // preload next group's flags

        #pragma unroll
        for (int k = 0; k < 8; k++) {
            int nslot = (t + k + 1) & (RING - 1);
            const float4* sp = reinterpret_cast<const float4*>(&ring[nslot][lane * 8]);
            float4 nq0 = sp[0], nq1 = sp[1];
            CTC_STEP(q0, q1);
            if (k == 3 || k == 7) CTC_RENORM();
            q0 = nq0; q1 = nq1;
        }
    }
    // Tail: all remaining rows (t..nsteps) are already filled & flagged.
    if (t <= nsteps) {
        CP_WAIT_ALL();
        for (; t <= nsteps; t++) {
            CTC_STEP(q0, q1);
            int nslot = (t + 1) & (RING - 1);   // contents unused past nsteps
            const float4* sp = reinterpret_cast<const float4*>(&ring[nslot][lane * 8]);
            q0 = sp[0]; q1 = sp[1];
        }
    }
#undef CTC_STEP
#undef CTC_RENORM

    // end_ll over alpha[2*tl] and alpha[max(2*tl-1,0)]
    int s1 = 2 * tl;
    int s2 = (2 * tl - 1 > 0) ? (2 * tl - 1) : 0;
    int lane1 = s1 >> 3, slot1 = s1 & 7;
    int lane2 = s2 >> 3, slot2 = s2 & 7;
    float v1 = a[0], v2 = a[0];
    #pragma unroll
    for (int j = 1; j < 8; j++) { v1 = (slot1 == j) ? a[j] : v1;
                                  v2 = (slot2 == j) ? a[j] : v2; }
    int   E1 = __shfl_sync(FULLMASK, El, lane1);
    int   E2 = __shfl_sync(FULLMASK, El, lane2);
    v1 = __shfl_sync(FULLMASK, v1, lane1);
    v2 = __shfl_sync(FULLMASK, v2, lane2);

    if (lane == 0) {
        float l1 = (v1 > 0.f) ? (log2f(v1) + (float)E1) : -3.0e38f;
        float l2 = (v2 > 0.f) ? (log2f(v2) + (float)E2) : -3.0e38f;
        float mx = fmaxf(l1, l2);
        float loss;
        if (mx < -2.0e38f) {
            loss = 0.f;                    // zero_infinity: p == 0
        } else {
            float tot2 = mx + log2f(exp2f(l1 - mx) + exp2f(l2 - mx));
            loss = -tot2 * LN2_F;
        }
        g_loss[b] = loss / (float)tl;
    }
}

// ---------------------------------------------------------------------------
// Kernel 2: deterministic batch-mean reduction (single warp).
// ---------------------------------------------------------------------------
__global__ void reduce_loss_kernel(float* __restrict__ out, int B)
{
    float v = 0.f;
    for (int i = threadIdx.x; i < B; i += 32) v += g_loss[i];
    #pragma unroll
    for (int o = 16; o; o >>= 1) v += __shfl_xor_sync(FULLMASK, v, o);
    if (threadIdx.x == 0) out[0] = v / (float)B;
}

// ---------------------------------------------------------------------------
extern "C" void kernel_launch(void* const* d_in, const int* in_sizes, int n_in,
                              void* d_out, int out_size)
{
    const float* pred = (const float*)d_in[0];
    const int*   plen = (const int*)d_in[1];
    const int*   gt   = (const int*)d_in[2];
    const int*   gtl  = (const int*)d_in[3];

    const int B  = in_sizes[1];
    const int L  = in_sizes[2] / B;
    const int T  = in_sizes[0] / (B * VOCAB);
    const int S  = 2 * L + 1;
    const int TP = (T + 39) & ~7;          // padded rows, multiple of 8
    const int NT = B * T;

    const int nflag = B * TP;
    init_flags_kernel<<<(nflag + 255) / 256, 256>>>(B, T, TP);

    const int prod_ctas = (NT + 7) / 8;
    fused_kernel<<<B + prod_ctas, 256>>>(pred, plen, gt, gtl, B, T, TP, L, S, NT);

    reduce_loss_kernel<<<1, 32>>>((float*)d_out, B);
}

// round 9
// speedup vs baseline: 1.8377x; 1.8377x over previous
#include <cuda_runtime.h>
#include <math_constants.h>
#include <cstdint>

// Shapes: V=1024 fixed; B,L,T from in_sizes. Scratch for B<=64, T<=1024, S<=256.
#define VOCAB      1024
#define MAXB       64
#define MAXTP      1056          // padded T rows (T + 32 prefetch slack)
#define SP         256           // padded extended-state stride (>= S = 2L+1), 8 per lane
#define RING       32            // smem ring slots (rows) per warp
#define DIST       28            // prefetch distance (rows ahead)
#define FULLMASK   0xffffffffu

#define LOG2E_F 1.4426950408889634f
#define LN2_F   0.6931471805599453f

typedef unsigned long long ull;

static __device__ __forceinline__ float fex2(float x) {
    float y; asm("ex2.approx.f32 %0, %1;" : "=f"(y) : "f"(x)); return y;
}

#define CP16(sm, gp) \
    asm volatile("cp.async.cg.shared.global [%0], [%1], 16;" :: "r"(sm), "l"(gp))
#define CP_COMMIT() \
    asm volatile("cp.async.commit_group;" ::: "memory")
#define CP_WAIT_26() \
    asm volatile("cp.async.wait_group 26;" ::: "memory")
#define CP_WAIT_27() \
    asm volatile("cp.async.wait_group 27;" ::: "memory")
#define CP_WAIT_ALL() \
    asm volatile("cp.async.wait_all;" ::: "memory")

// Scratch: per-(b,t) extended-label PROBABILITIES (softmax, gathered), padded.
__device__ float g_p[(size_t)MAXB * MAXTP * SP];
__device__ float g_loss[MAXB];

// ---------------------------------------------------------------------------
// Pass 1: per-row softmax + gather. ONE WARP PER ROW (32 values/lane in
// registers, MLP=8), no SMEM, no CTA barriers. 8 rows per 256-thread CTA.
// ---------------------------------------------------------------------------
__global__ void __launch_bounds__(256)
softmax_gather_kernel(const float* __restrict__ pred,
                      const int*   __restrict__ gt,
                      int NT, int T, int TP, int L, int S)
{
    const int row  = blockIdx.x * 8 + (threadIdx.x >> 5);
    if (row >= NT) return;
    const int lane = threadIdx.x & 31;
    const int b    = row / T;
    const int t    = row - b * T;

    const float* __restrict__ p = pred + (size_t)row * VOCAB;

    float4 v[8];
    #pragma unroll
    for (int k = 0; k < 8; k++)
        v[k] = *reinterpret_cast<const float4*>(p + lane * 4 + k * 128);

    float mx = -CUDART_INF_F;
    #pragma unroll
    for (int k = 0; k < 8; k++)
        mx = fmaxf(mx, fmaxf(fmaxf(v[k].x, v[k].y), fmaxf(v[k].z, v[k].w)));
    #pragma unroll
    for (int o = 16; o; o >>= 1)
        mx = fmaxf(mx, __shfl_xor_sync(FULLMASK, mx, o));
    const float c = mx * LOG2E_F;

    float sum = 0.f;
    #pragma unroll
    for (int k = 0; k < 8; k++) {
        sum += fex2(fmaf(v[k].x, LOG2E_F, -c)) + fex2(fmaf(v[k].y, LOG2E_F, -c))
             + fex2(fmaf(v[k].z, LOG2E_F, -c)) + fex2(fmaf(v[k].w, LOG2E_F, -c));
    }
    #pragma unroll
    for (int o = 16; o; o >>= 1)
        sum += __shfl_xor_sync(FULLMASK, sum, o);
    const float inv = __frcp_rn(sum);

    float* __restrict__ out = g_p + ((size_t)b * TP + t) * SP;
    const int* __restrict__ gtb = gt + (size_t)b * L;
    float val[8];
    #pragma unroll
    for (int j = 0; j < 8; j++) {
        int s = lane * 8 + j;
        float r = 0.f;
        if (s < S) {
            int lab = 0;
            if (s & 1) {
                int idx = (s >> 1); if (idx > L - 1) idx = L - 1;
                lab = gtb[idx];
            }
            r = fex2(fmaf(__ldg(p + lab), LOG2E_F, -c)) * inv;
        }
        val[j] = r;
    }
    *reinterpret_cast<float4*>(out + lane * 8)     = make_float4(val[0], val[1], val[2], val[3]);
    *reinterpret_cast<float4*>(out + lane * 8 + 4) = make_float4(val[4], val[5], val[6], val[7]);
}

// ---------------------------------------------------------------------------
// Pass 2: CTC forward recursion, prob domain, PER-LANE block floating point.
// One warp per CTA/batch; lane l owns states [8l, 8l+8).
// Key reductions vs R6:
//  - states 8l+{0,2,4,6} are ALWAYS blank (even) -> skip mask is exactly 0:
//    the u6 shuffle and 4 FFMAs are deleted (bit-identical math).
//  - renorm every 8 steps (values shrink ~2^-80 between renorms: all normal
//    floats, per-lane scaling exactness unchanged).
// cp.async SMEM ring (depth 28) hides DRAM latency on evicted g_p.
// ---------------------------------------------------------------------------
__global__ void __launch_bounds__(32)
ctc_forward_kernel(const int* __restrict__ plen,
                   const int* __restrict__ gt,
                   const int* __restrict__ gtl,
                   int B, int T, int TP, int L, int S)
{
    __shared__ float ring[RING][SP];     // 32 KB

    const int b    = blockIdx.x;
    const int lane = threadIdx.x;
    const int ilen = min(plen[b], T);
    const int tl   = gtl[b];
    const float* __restrict__ Pb = g_p + (size_t)b * TP * SP + lane * 8;
    const int* __restrict__ gtb = gt + (size_t)b * L;
    const unsigned int rb =
        (unsigned int)__cvta_generic_to_shared(ring) + (unsigned int)(lane * 32);

    // Skip masks for the 4 odd (label) states only.
    float m1, m3, m5, m7;
    {
        float mm[4];
        #pragma unroll
        for (int jj = 0; jj < 4; jj++) {
            int s = lane * 8 + 2 * jj + 1;
            float v = 0.f;
            if (s >= 2 && s < S) {
                int lab = gtb[s >> 1], lm2 = gtb[(s >> 1) - 1];
                v = (lab != 0 && lab != lm2) ? 1.f : 0.f;
            }
            mm[jj] = v;
        }
        m1 = mm[0]; m3 = mm[1]; m5 = mm[2]; m7 = mm[3];
    }

    // alpha(t=0)
    float a[8];
    #pragma unroll
    for (int j = 0; j < 8; j++) a[j] = 0.f;
    if (lane == 0) {
        float4 q = *reinterpret_cast<const float4*>(Pb);
        a[0] = q.x;
        a[1] = (tl > 0) ? q.y : 0.f;
    }

    int   El = 0;                          // per-lane exponent
    float f  = (lane == 0) ? 0.f : 1.f;    // 2^(El_left - El); lane 0 has no left
    const int nsteps = ilen - 1;           // recursion runs t = 1 .. ilen-1

#define CTC_STEP(Q0, Q1)                                                    \
    do {                                                                     \
        float u7  = __shfl_up_sync(FULLMASK, a[7], 1);                       \
        float u7f = u7 * f;                                                  \
        float n0 = (a[0] + u7f)               * (Q0).x;                      \
        float n1 = fmaf(m1, u7f,  a[1] + a[0]) * (Q0).y;                     \
        float n2 = (a[2] + a[1])              * (Q0).z;                      \
        float n3 = fmaf(m3, a[1], a[3] + a[2]) * (Q0).w;                     \
        float n4 = (a[4] + a[3])              * (Q1).x;                      \
        float n5 = fmaf(m5, a[3], a[5] + a[4]) * (Q1).y;                     \
        float n6 = (a[6] + a[5])              * (Q1).z;                      \
        float n7 = fmaf(m7, a[5], a[7] + a[6]) * (Q1).w;                     \
        a[0]=n0; a[1]=n1; a[2]=n2; a[3]=n3; a[4]=n4; a[5]=n5; a[6]=n6; a[7]=n7; \
    } while (0)

#define CTC_RENORM()                                                        \
    do {                                                                     \
        float mx = fmaxf(fmaxf(fmaxf(a[0], a[1]), fmaxf(a[2], a[3])),       \
                         fmaxf(fmaxf(a[4], a[5]), fmaxf(a[6], a[7])));       \
        bool nz = (mx > 0.f);                                                \
        int  e  = nz ? ((__float_as_int(mx) >> 23) - 127) : 0;               \
        int  Elp = El + e;                                                   \
        int  Eleft = __shfl_up_sync(FULLMASK, Elp, 1);                       \
        if (!nz && lane > 0) Elp = Eleft;      /* adopt neighbor's scale */  \
        if (nz) {                                                            \
            float sc = __int_as_float((127 - e) << 23);                      \
            _Pragma("unroll")                                                \
            for (int j = 0; j < 8; j++) a[j] *= sc;                          \
        }                                                                    \
        El = Elp;                                                            \
        int El2 = __shfl_up_sync(FULLMASK, El, 1);                           \
        int dE  = El2 - El;                                                  \
        if (lane == 0 || dE < -126) f = 0.f;                                 \
        else f = __int_as_float((min(dE, 126) + 127) << 23);                 \
    } while (0)

    // Prologue: fill ring with rows 1..DIST
    {
        const float* gp = Pb + SP;           // row 1
        #pragma unroll 4
        for (int r = 1; r <= DIST; r++) {
            unsigned int sa = rb + (unsigned int)((r & (RING - 1)) * (SP * 4));
            CP16(sa, gp); CP16(sa + 16, gp + 4);
            CP_COMMIT();
            gp += SP;
        }
    }

    float4 q0 = make_float4(0.f, 0.f, 0.f, 0.f), q1 = q0;
    if (nsteps >= 1) {
        CP_WAIT_27();                        // row 1 landed
        const float4* sp = reinterpret_cast<const float4*>(&ring[1][lane * 8]);
        q0 = sp[0]; q1 = sp[1];
    }

    const float* fill_ptr = Pb + (size_t)(1 + DIST) * SP;
    int t = 1;
    for (; t + 7 <= nsteps; t += 8) {
        #pragma unroll
        for (int k = 0; k < 8; k++) {
            CP_WAIT_26();                    // row t+k+1 landed
            int nslot = (t + k + 1) & (RING - 1);
            const float4* sp = reinterpret_cast<const float4*>(&ring[nslot][lane * 8]);
            float4 nq0 = sp[0], nq1 = sp[1];
            // refill: row t+k+DIST into its slot
            {
                unsigned int sa = rb +
                    (unsigned int)((((t + k + DIST) & (RING - 1))) * (SP * 4));
                const float* gp = fill_ptr + (size_t)k * SP;
                CP16(sa, gp); CP16(sa + 16, gp + 4);
                CP_COMMIT();
            }
            CTC_STEP(q0, q1);
            if (k == 7) CTC_RENORM();
            q0 = nq0; q1 = nq1;
        }
        fill_ptr += 8 * SP;
    }
    // Tail: all remaining rows were prefetched into the ring already.
    if (t <= nsteps) {
        CP_WAIT_ALL();
        for (; t <= nsteps; t++) {
            CTC_STEP(q0, q1);
            int nslot = (t + 1) & (RING - 1);   // contents unused past nsteps
            const float4* sp = reinterpret_cast<const float4*>(&ring[nslot][lane * 8]);
            q0 = sp[0]; q1 = sp[1];
        }
    }
#undef CTC_STEP
#undef CTC_RENORM

    // end_ll over alpha[2*tl] and alpha[max(2*tl-1,0)]
    int s1 = 2 * tl;
    int s2 = (2 * tl - 1 > 0) ? (2 * tl - 1) : 0;
    int lane1 = s1 >> 3, slot1 = s1 & 7;
    int lane2 = s2 >> 3, slot2 = s2 & 7;
    float v1 = a[0], v2 = a[0];
    #pragma unroll
    for (int j = 1; j < 8; j++) { v1 = (slot1 == j) ? a[j] : v1;
                                  v2 = (slot2 == j) ? a[j] : v2; }
    int   E1 = __shfl_sync(FULLMASK, El, lane1);
    int   E2 = __shfl_sync(FULLMASK, El, lane2);
    v1 = __shfl_sync(FULLMASK, v1, lane1);
    v2 = __shfl_sync(FULLMASK, v2, lane2);

    if (lane == 0) {
        float l1 = (v1 > 0.f) ? (log2f(v1) + (float)E1) : -3.0e38f;
        float l2 = (v2 > 0.f) ? (log2f(v2) + (float)E2) : -3.0e38f;
        float mx = fmaxf(l1, l2);
        float loss;
        if (mx < -2.0e38f) {
            loss = 0.f;                    // zero_infinity: p == 0
        } else {
            float tot2 = mx + log2f(exp2f(l1 - mx) + exp2f(l2 - mx));
            loss = -tot2 * LN2_F;
        }
        g_loss[b] = loss / (float)tl;
    }
}

// ---------------------------------------------------------------------------
// Pass 3: deterministic batch-mean reduction (single warp).
// ---------------------------------------------------------------------------
__global__ void reduce_loss_kernel(float* __restrict__ out, int B)
{
    float v = 0.f;
    for (int i = threadIdx.x; i < B; i += 32) v += g_loss[i];
    #pragma unroll
    for (int o = 16; o; o >>= 1) v += __shfl_xor_sync(FULLMASK, v, o);
    if (threadIdx.x == 0) out[0] = v / (float)B;
}

// ---------------------------------------------------------------------------
extern "C" void kernel_launch(void* const* d_in, const int* in_sizes, int n_in,
                              void* d_out, int out_size)
{
    const float* pred = (const float*)d_in[0];
    const int*   plen = (const int*)d_in[1];
    const int*   gt   = (const int*)d_in[2];
    const int*   gtl  = (const int*)d_in[3];

    const int B  = in_sizes[1];
    const int L  = in_sizes[2] / B;
    const int T  = in_sizes[0] / (B * VOCAB);
    const int S  = 2 * L + 1;
    const int TP = T + 32;                // padded rows (prefetch slack)
    const int NT = B * T;

    softmax_gather_kernel<<<(NT + 7) / 8, 256>>>(pred, gt, NT, T, TP, L, S);
    ctc_forward_kernel<<<B, 32>>>(plen, gt, gtl, B, T, TP, L, S);
    reduce_loss_kernel<<<1, 32>>>((float*)d_out, B);
}